// round 12
// baseline (speedup 1.0000x reference)
#include <cuda_runtime.h>
#include <cuda_fp16.h>
#include <cstdint>
#include <math.h>

#define BB 32
#define TT 2048
#define DD 512
#define UU 512

#define TROWS 32               // t-rows per k_score CTA
#define TCH (TT / TROWS)       // 64 chunks per batch

// ---- scratch ----
__device__ float g_hpart[BB * 4 * UU];   // split-k h2 partials (+b1+b2 in ks=0)
__device__ float g_zpart[BB * TCH];
__device__ float g_part[BB * TCH * DD];
__device__ __half g_w16[DD * UU];        // W1 fp16, native [d][u] layout

// ---------------- helpers ----------------
static __device__ __forceinline__ unsigned pack2h(__half a, __half b) {
    return (unsigned)__half_as_ushort(a) |
           ((unsigned)__half_as_ushort(b) << 16);
}
static __device__ __forceinline__ float fast_tanh(float x) {
    float e = __expf(2.f * x);
    return 1.f - __fdividef(2.f, e + 1.f);
}
static __device__ __forceinline__ void mma16816(float* c, const unsigned* a, const unsigned* b) {
    asm volatile(
        "mma.sync.aligned.m16n8k16.row.col.f32.f16.f16.f32 "
        "{%0,%1,%2,%3}, {%4,%5,%6,%7}, {%8,%9}, {%0,%1,%2,%3};"
        : "+f"(c[0]), "+f"(c[1]), "+f"(c[2]), "+f"(c[3])
        : "r"(a[0]), "r"(a[1]), "r"(a[2]), "r"(a[3]), "r"(b[0]), "r"(b[1]));
}
static __device__ __forceinline__ void ldm4(unsigned* r, const void* p) {
    unsigned addr = (unsigned)__cvta_generic_to_shared(p);
    asm volatile(
        "ldmatrix.sync.aligned.m8n8.x4.shared.b16 {%0,%1,%2,%3}, [%4];"
        : "=r"(r[0]), "=r"(r[1]), "=r"(r[2]), "=r"(r[3])
        : "r"(addr));
}
static __device__ __forceinline__ void ldm4t(unsigned* r, const void* p) {
    unsigned addr = (unsigned)__cvta_generic_to_shared(p);
    asm volatile(
        "ldmatrix.sync.aligned.m8n8.x4.trans.shared.b16 {%0,%1,%2,%3}, [%4];"
        : "=r"(r[0]), "=r"(r[1]), "=r"(r[2]), "=r"(r[3])
        : "r"(addr));
}
static __device__ __forceinline__ void cp16(void* dst, const void* src) {
    unsigned d = (unsigned)__cvta_generic_to_shared(dst);
    asm volatile("cp.async.cg.shared.global [%0], [%1], 16;"
                 :: "r"(d), "l"(src) : "memory");
}
static __device__ __forceinline__ void cp_commit() {
    asm volatile("cp.async.commit_group;" ::: "memory");
}
static __device__ __forceinline__ void cp_wait2() {
    asm volatile("cp.async.wait_group 2;" ::: "memory");
}
static __device__ __forceinline__ void cp_wait1() {
    asm volatile("cp.async.wait_group 1;" ::: "memory");
}
static __device__ __forceinline__ void cp_wait0() {
    asm volatile("cp.async.wait_group 0;" ::: "memory");
}

// smem layout (halves unless noted)
#define PADA 520
#define PADB2 136                  // 272 B row stride, mod 128 = 16 -> conflict-free
#define NSTAGE 4
#define OFF_HB   0
#define OFF_VS   512
#define OFF_RED  1024              // 128 floats
#define OFF_B    2048
#define B_STAGE_H (32 * PADB2)                         // 4352 halves = 8704 B
#define OFF_A    (OFF_B + NSTAGE * B_STAGE_H * 2)      // 36864
#define SMEM_TOTAL (OFF_A + TROWS * PADA * 2)          // 36864 + 33280 = 70144

// ---------------------------------------------------------------------------
// Kernel A: fused (W1 fp32->fp16 elementwise) + (h2 split-k partials, ILP=4)
// ---------------------------------------------------------------------------
__global__ void k_pre(const float* __restrict__ W1,
                      const float* __restrict__ last,
                      const float* __restrict__ W2,
                      const float* __restrict__ b1,
                      const float* __restrict__ b2) {
    if (blockIdx.x < 128) {
        int gidx = blockIdx.x * 2048 + threadIdx.x * 4;
        float4 v = *(const float4*)(W1 + gidx);
        uint2 hv;
        hv.x = pack2h(__float2half_rn(v.x), __float2half_rn(v.y));
        hv.y = pack2h(__float2half_rn(v.z), __float2half_rn(v.w));
        *(uint2*)(g_w16 + gidx) = hv;
    } else {
        int bid = blockIdx.x - 128;
        int b  = bid >> 2;
        int ks = bid & 3;
        int u  = threadIdx.x;
        __shared__ float sl[128];
        if (u < 128) sl[u] = last[b * DD + ks * 128 + u];
        __syncthreads();
        const float* w2p = W2 + (size_t)(ks * 128) * UU + u;
        float a0 = 0.f, a1 = 0.f, a2 = 0.f, a3 = 0.f;
#pragma unroll 8
        for (int d = 0; d < 128; d += 4) {
            a0 += sl[d + 0] * w2p[(size_t)(d + 0) * UU];
            a1 += sl[d + 1] * w2p[(size_t)(d + 1) * UU];
            a2 += sl[d + 2] * w2p[(size_t)(d + 2) * UU];
            a3 += sl[d + 3] * w2p[(size_t)(d + 3) * UU];
        }
        float acc = (a0 + a1) + (a2 + a3);
        if (ks == 0) acc += b1[u] + b2[u];
        g_hpart[(b * 4 + ks) * UU + u] = acc;
    }
}

// ---------------------------------------------------------------------------
// Kernel B: scores + fused partial context.  CTA = 32t x 512u x 512k.
// A fp16 resident; B = W1 fp16 native [k][u] rows, 4-stage cp.async ring,
// ldmatrix.trans consumption, one barrier per k-chunk.
// ---------------------------------------------------------------------------
__global__ __launch_bounds__(256, 2) void k_score(
    const float* __restrict__ full, const float* __restrict__ V) {
    extern __shared__ __align__(16) char smem[];
    float* hb_s = (float*)(smem + OFF_HB);
    float* vs_s = (float*)(smem + OFF_VS);
    float* red  = (float*)(smem + OFF_RED);
    __half* sB  = (__half*)(smem + OFF_B);
    __half* sA  = (__half*)(smem + OFF_A);

    const int tid = threadIdx.x;
    const int wid = tid >> 5;
    const int lane = tid & 31;
    const int g = lane >> 2;
    const int t = lane & 3;
    const int mw = wid >> 2;        // 0..1 -> 16-row m-tile
    const int nw = wid & 3;         // 0..3 -> 32-col u-tile
    const int mbase = mw * 16;
    const int nbase = nw * 32;

    const int b  = blockIdx.y;
    const int tc = blockIdx.x;
    const int t0 = tc * TROWS;

    const int tile = lane >> 3;
    const int rr = lane & 7;
    const int a_lane_off = ((tile & 1) * 8 + rr) * PADA + ((tile >> 1) & 1) * 8;
    const int bt_lane_off = ((tile & 1) * 8 + rr) * PADB2 + ((tile >> 1) & 1) * 8;

    auto issueB = [&](int gc, int slot) {
        const int u0 = (gc >> 4) * 128;
        const int k0 = (gc & 15) * 32;
#pragma unroll
        for (int j = 0; j < 2; ++j) {
            int o   = tid + j * 256;        // 0..511
            int row = o >> 4;               // k row 0..31
            int q   = o & 15;               // 16B chunk within 256B row
            const __half* src = g_w16 + (size_t)(k0 + row) * UU + u0 + q * 8;
            __half* dst = sB + slot * B_STAGE_H + row * PADB2 + q * 8;
            cp16(dst, src);
        }
        cp_commit();
    };

    issueB(0, 0);
    issueB(1, 1);
    issueB(2, 2);

    {
        const float* Ab = full + ((size_t)(b * TT + t0)) * DD;
#pragma unroll
        for (int it = 0; it < 16; ++it) {
            int idx = tid + it * 256;      // 0..4095 float4s
            int r = idx >> 7;
            int q = idx & 127;
            float4 v4 = *(const float4*)(Ab + (size_t)r * DD + q * 4);
            uint2 hv;
            hv.x = pack2h(__float2half_rn(v4.x), __float2half_rn(v4.y));
            hv.y = pack2h(__float2half_rn(v4.z), __float2half_rn(v4.w));
            *(uint2*)(sA + r * PADA + q * 4) = hv;
        }
    }

    float s[2];
    s[0] = 0.f; s[1] = 0.f;
    float acc[16];

    for (int gc = 0; gc < 64; ++gc) {
        const int slot = gc & 3;
        if (gc <= 61) cp_wait2();
        else if (gc == 62) cp_wait1();
        else cp_wait0();
        __syncthreads();

        if ((gc & 15) == 0) {
            int uc = gc >> 4;
            if (tid < 128) {
                int u = uc * 128 + tid;
                hb_s[tid] = g_hpart[(b * 4 + 0) * UU + u]
                          + g_hpart[(b * 4 + 1) * UU + u]
                          + g_hpart[(b * 4 + 2) * UU + u]
                          + g_hpart[(b * 4 + 3) * UU + u];
                vs_s[tid] = V[u];
            }
#pragma unroll
            for (int i = 0; i < 16; ++i) acc[i] = 0.f;
        }
        if (gc + 3 < 64) issueB(gc + 3, (gc + 3) & 3);

        const __half* Bh = sB + slot * B_STAGE_H;
        const int k0 = (gc & 15) * 32;
#pragma unroll
        for (int kk = 0; kk < 32; kk += 16) {
            unsigned bh[8];
#pragma unroll
            for (int p = 0; p < 2; ++p)
                ldm4t(bh + 4 * p, Bh + kk * PADB2 + nbase + p * 16 + bt_lane_off);
            unsigned ah[4];
            ldm4(ah, sA + mbase * PADA + k0 + kk + a_lane_off);
#pragma unroll
            for (int nt = 0; nt < 4; ++nt)
                mma16816(acc + nt * 4, ah, bh + 2 * nt);
        }

        if ((gc & 15) == 15) {
#pragma unroll
            for (int nt = 0; nt < 4; ++nt) {
                const float* cc = acc + nt * 4;
                int n0 = nbase + nt * 8 + 2 * t;
                s[0] += fast_tanh(cc[0] + hb_s[n0]) * vs_s[n0]
                      + fast_tanh(cc[1] + hb_s[n0 + 1]) * vs_s[n0 + 1];
                s[1] += fast_tanh(cc[2] + hb_s[n0]) * vs_s[n0]
                      + fast_tanh(cc[3] + hb_s[n0 + 1]) * vs_s[n0 + 1];
            }
        }
    }

    // ---- score reduce: t lanes (width 4), then 4 nw-warps via smem ----
#pragma unroll
    for (int i = 0; i < 2; ++i) {
        float v = s[i];
        v += __shfl_xor_sync(0xffffffffu, v, 1, 4);
        v += __shfl_xor_sync(0xffffffffu, v, 2, 4);
        if (t == 0) {
            int row = mbase + i * 8 + g;
            red[nw * 32 + row] = v;
        }
    }
    __syncthreads();

    // ---- exp(score) per row (bV cancels in softmax) ----
    float* ws = hb_s;              // reuse
    if (tid < TROWS) {
        float sum = red[tid] + red[32 + tid] + red[64 + tid] + red[96 + tid];
        ws[tid] = expf(sum);
    }
    __syncthreads();

    if (tid == 0) {
        float z = 0.f;
#pragma unroll
        for (int i = 0; i < TROWS; ++i) z += ws[i];
        g_zpart[b * TCH + tc] = z;
    }

    // ---- partial weighted context from smem A tile (fp16) ----
    {
        float2 cacc = make_float2(0.f, 0.f);
#pragma unroll 8
        for (int r = 0; r < TROWS; ++r) {
            __half2 a = *(const __half2*)(sA + r * PADA + 2 * tid);
            float2 f = __half22float2(a);
            float w = ws[r];
            cacc.x += w * f.x;
            cacc.y += w * f.y;
        }
        ((float2*)(g_part + ((size_t)(b * TCH + tc)) * DD))[tid] = cacc;
    }
}

// ---------------------------------------------------------------------------
// Kernel C: combine partials + Z, divide.  grid (4, BB) x 128 thr.
// ---------------------------------------------------------------------------
__global__ void k_combine(float* __restrict__ out) {
    int b = blockIdx.y;
    int d = blockIdx.x * 128 + threadIdx.x;
    __shared__ float zs;
    if (threadIdx.x == 0) {
        float z = 0.f;
#pragma unroll
        for (int tc = 0; tc < TCH; ++tc) z += g_zpart[b * TCH + tc];
        zs = z;
    }
    __syncthreads();
    float a0 = 0.f, a1 = 0.f;
#pragma unroll
    for (int tc = 0; tc < TCH; tc += 2) {
        a0 += g_part[((size_t)(b * TCH + tc)) * DD + d];
        a1 += g_part[((size_t)(b * TCH + tc + 1)) * DD + d];
    }
    out[b * DD + d] = (a0 + a1) / zs;
}

// ---------------------------------------------------------------------------
extern "C" void kernel_launch(void* const* d_in, const int* in_sizes, int n_in,
                              void* d_out, int out_size) {
    const float* full = (const float*)d_in[0];
    const float* last = (const float*)d_in[1];
    const float* W1   = (const float*)d_in[2];
    const float* b1   = (const float*)d_in[3];
    const float* W2   = (const float*)d_in[4];
    const float* b2   = (const float*)d_in[5];
    const float* V    = (const float*)d_in[6];
    float* out = (float*)d_out;

    cudaFuncSetAttribute(k_score, cudaFuncAttributeMaxDynamicSharedMemorySize,
                         SMEM_TOTAL);

    k_pre<<<256, 512>>>(W1, last, W2, b1, b2);

    dim3 gScore(TCH, BB);
    k_score<<<gScore, 256, SMEM_TOTAL>>>(full, V);

    dim3 gComb(4, BB);
    k_combine<<<gComb, 128>>>(out);
}

// round 13
// speedup vs baseline: 1.6337x; 1.6337x over previous
#include <cuda_runtime.h>
#include <cuda_fp16.h>
#include <cstdint>
#include <math.h>

#define BB 32
#define TT 2048
#define DD 512
#define UU 512

#define TROWS 64
#define TCH (TT / TROWS)       // 32 chunks per batch

// ---- scratch ----
__device__ float g_hpart[BB * 4 * UU];   // split-k h2 partials (+b1+b2 in ks=0)
__device__ float g_spart[BB * TCH * 2 * TROWS];  // per-u-half row scores
__device__ int   g_flag[BB * TCH];
__device__ float g_zpart[BB * TCH];
__device__ float g_part[BB * TCH * DD];
__device__ __half g_w16[DD * UU];        // W1 fp16, native [d][u] layout

// ---------------- helpers ----------------
static __device__ __forceinline__ unsigned pack2h(__half a, __half b) {
    return (unsigned)__half_as_ushort(a) |
           ((unsigned)__half_as_ushort(b) << 16);
}
static __device__ __forceinline__ float fast_tanh(float x) {
    float e = __expf(2.f * x);
    return 1.f - __fdividef(2.f, e + 1.f);
}
static __device__ __forceinline__ void mma16816(float* c, const unsigned* a, const unsigned* b) {
    asm volatile(
        "mma.sync.aligned.m16n8k16.row.col.f32.f16.f16.f32 "
        "{%0,%1,%2,%3}, {%4,%5,%6,%7}, {%8,%9}, {%0,%1,%2,%3};"
        : "+f"(c[0]), "+f"(c[1]), "+f"(c[2]), "+f"(c[3])
        : "r"(a[0]), "r"(a[1]), "r"(a[2]), "r"(a[3]), "r"(b[0]), "r"(b[1]));
}
static __device__ __forceinline__ void ldm4(unsigned* r, const void* p) {
    unsigned addr = (unsigned)__cvta_generic_to_shared(p);
    asm volatile(
        "ldmatrix.sync.aligned.m8n8.x4.shared.b16 {%0,%1,%2,%3}, [%4];"
        : "=r"(r[0]), "=r"(r[1]), "=r"(r[2]), "=r"(r[3])
        : "r"(addr));
}
static __device__ __forceinline__ void ldm4t(unsigned* r, const void* p) {
    unsigned addr = (unsigned)__cvta_generic_to_shared(p);
    asm volatile(
        "ldmatrix.sync.aligned.m8n8.x4.trans.shared.b16 {%0,%1,%2,%3}, [%4];"
        : "=r"(r[0]), "=r"(r[1]), "=r"(r[2]), "=r"(r[3])
        : "r"(addr));
}
static __device__ __forceinline__ void cp16(void* dst, const void* src) {
    unsigned d = (unsigned)__cvta_generic_to_shared(dst);
    asm volatile("cp.async.cg.shared.global [%0], [%1], 16;"
                 :: "r"(d), "l"(src) : "memory");
}
static __device__ __forceinline__ void cp_commit() {
    asm volatile("cp.async.commit_group;" ::: "memory");
}
static __device__ __forceinline__ void cp_wait2() {
    asm volatile("cp.async.wait_group 2;" ::: "memory");
}
static __device__ __forceinline__ void cp_wait1() {
    asm volatile("cp.async.wait_group 1;" ::: "memory");
}
static __device__ __forceinline__ void cp_wait0() {
    asm volatile("cp.async.wait_group 0;" ::: "memory");
}

// smem layout (halves unless noted)
#define PADA 520
#define PADB2 136
#define NSTAGE 4
#define OFF_HB   0
#define OFF_VS   512
#define OFF_RED  1024              // 256 floats
#define OFF_B    2048
#define B_STAGE_H (32 * PADB2)                         // 8704 B
#define OFF_A    (OFF_B + NSTAGE * B_STAGE_H * 2)      // 36864
#define SMEM_TOTAL (OFF_A + TROWS * PADA * 2)          // 103424 B

// ---------------------------------------------------------------------------
// Kernel A: W1 fp32->fp16 convert + h2 split-k partials + flag reset
// ---------------------------------------------------------------------------
__global__ void k_pre(const float* __restrict__ W1,
                      const float* __restrict__ last,
                      const float* __restrict__ W2,
                      const float* __restrict__ b1,
                      const float* __restrict__ b2) {
    if (blockIdx.x < 128) {
        int gidx = blockIdx.x * 2048 + threadIdx.x * 4;
        float4 v = *(const float4*)(W1 + gidx);
        uint2 hv;
        hv.x = pack2h(__float2half_rn(v.x), __float2half_rn(v.y));
        hv.y = pack2h(__float2half_rn(v.z), __float2half_rn(v.w));
        *(uint2*)(g_w16 + gidx) = hv;
    } else if (blockIdx.x < 256) {
        int bid = blockIdx.x - 128;
        int b  = bid >> 2;
        int ks = bid & 3;
        int u  = threadIdx.x;
        __shared__ float sl[128];
        if (u < 128) sl[u] = last[b * DD + ks * 128 + u];
        __syncthreads();
        const float* w2p = W2 + (size_t)(ks * 128) * UU + u;
        float a0 = 0.f, a1 = 0.f, a2 = 0.f, a3 = 0.f;
#pragma unroll 8
        for (int d = 0; d < 128; d += 4) {
            a0 += sl[d + 0] * w2p[(size_t)(d + 0) * UU];
            a1 += sl[d + 1] * w2p[(size_t)(d + 1) * UU];
            a2 += sl[d + 2] * w2p[(size_t)(d + 2) * UU];
            a3 += sl[d + 3] * w2p[(size_t)(d + 3) * UU];
        }
        float acc = (a0 + a1) + (a2 + a3);
        if (ks == 0) acc += b1[u] + b2[u];
        g_hpart[(b * 4 + ks) * UU + u] = acc;
    } else {
        // flag reset (runs every launch, before k_score in-stream)
        g_flag[threadIdx.x * 2]     = 0;
        g_flag[threadIdx.x * 2 + 1] = 0;
    }
}

// ---------------------------------------------------------------------------
// Kernel B: CTA = 64t x 256u (u-half) x 512k.  A fp16 resident; B streamed
// (4-stage cp.async ring, ldmatrix.trans).  Second-finishing CTA of each
// (b,tc) pair computes exp/Z/context from both u-half score partials.
// ---------------------------------------------------------------------------
__global__ __launch_bounds__(256, 2) void k_score(
    const float* __restrict__ full, const float* __restrict__ V) {
    extern __shared__ __align__(16) char smem[];
    float* hb_s = (float*)(smem + OFF_HB);
    float* vs_s = (float*)(smem + OFF_VS);
    float* red  = (float*)(smem + OFF_RED);
    __half* sB  = (__half*)(smem + OFF_B);
    __half* sA  = (__half*)(smem + OFF_A);
    __shared__ int isLast;

    const int tid = threadIdx.x;
    const int wid = tid >> 5;
    const int lane = tid & 31;
    const int g = lane >> 2;
    const int t = lane & 3;
    const int mw = wid >> 2;        // 0..1 -> 32-row m-tile
    const int nw = wid & 3;         // 0..3 -> 32-col u-tile
    const int mbase = mw * 32;
    const int nbase = nw * 32;

    const int b  = blockIdx.y;
    const int tc = blockIdx.x;
    const int uh = blockIdx.z;      // u-half 0/1
    const int t0 = tc * TROWS;
    const int ubase = uh * 256;

    const int tile = lane >> 3;
    const int rr = lane & 7;
    const int a_lane_off = ((tile & 1) * 8 + rr) * PADA + ((tile >> 1) & 1) * 8;
    const int bt_lane_off = ((tile & 1) * 8 + rr) * PADB2 + ((tile >> 1) & 1) * 8;

    auto issueB = [&](int gc, int slot) {
        const int u0 = ubase + (gc >> 4) * 128;
        const int k0 = (gc & 15) * 32;
#pragma unroll
        for (int j = 0; j < 2; ++j) {
            int o   = tid + j * 256;
            int row = o >> 4;
            int q   = o & 15;
            const __half* src = g_w16 + (size_t)(k0 + row) * UU + u0 + q * 8;
            __half* dst = sB + slot * B_STAGE_H + row * PADB2 + q * 8;
            cp16(dst, src);
        }
        cp_commit();
    };

    issueB(0, 0);
    issueB(1, 1);
    issueB(2, 2);

    {
        const float* Ab = full + ((size_t)(b * TT + t0)) * DD;
#pragma unroll
        for (int it = 0; it < 32; ++it) {
            int idx = tid + it * 256;
            int r = idx >> 7;
            int q = idx & 127;
            float4 v4 = *(const float4*)(Ab + (size_t)r * DD + q * 4);
            uint2 hv;
            hv.x = pack2h(__float2half_rn(v4.x), __float2half_rn(v4.y));
            hv.y = pack2h(__float2half_rn(v4.z), __float2half_rn(v4.w));
            *(uint2*)(sA + r * PADA + q * 4) = hv;
        }
    }

    float s[4];
#pragma unroll
    for (int i = 0; i < 4; ++i) s[i] = 0.f;
    float acc[32];

    for (int gc = 0; gc < 32; ++gc) {
        const int slot = gc & 3;
        if (gc <= 29) cp_wait2();
        else if (gc == 30) cp_wait1();
        else cp_wait0();
        __syncthreads();

        if ((gc & 15) == 0) {
            int uc = gc >> 4;
            if (tid < 128) {
                int u = ubase + uc * 128 + tid;
                hb_s[tid] = g_hpart[(b * 4 + 0) * UU + u]
                          + g_hpart[(b * 4 + 1) * UU + u]
                          + g_hpart[(b * 4 + 2) * UU + u]
                          + g_hpart[(b * 4 + 3) * UU + u];
                vs_s[tid] = V[u];
            }
#pragma unroll
            for (int i = 0; i < 32; ++i) acc[i] = 0.f;
        }
        if (gc + 3 < 32) issueB(gc + 3, (gc + 3) & 3);

        const __half* Bh = sB + slot * B_STAGE_H;
        const int k0 = (gc & 15) * 32;
#pragma unroll
        for (int kk = 0; kk < 32; kk += 16) {
            unsigned bh[8];
#pragma unroll
            for (int p = 0; p < 2; ++p)
                ldm4t(bh + 4 * p, Bh + kk * PADB2 + nbase + p * 16 + bt_lane_off);
#pragma unroll
            for (int mt = 0; mt < 2; ++mt) {
                unsigned ah[4];
                ldm4(ah, sA + (mbase + mt * 16) * PADA + k0 + kk + a_lane_off);
#pragma unroll
                for (int nt = 0; nt < 4; ++nt)
                    mma16816(acc + (mt * 4 + nt) * 4, ah, bh + 2 * nt);
            }
        }

        if ((gc & 15) == 15) {
#pragma unroll
            for (int mt = 0; mt < 2; ++mt) {
#pragma unroll
                for (int nt = 0; nt < 4; ++nt) {
                    const float* cc = acc + (mt * 4 + nt) * 4;
                    int n0 = nbase + nt * 8 + 2 * t;
                    s[mt * 2 + 0] += fast_tanh(cc[0] + hb_s[n0]) * vs_s[n0]
                                   + fast_tanh(cc[1] + hb_s[n0 + 1]) * vs_s[n0 + 1];
                    s[mt * 2 + 1] += fast_tanh(cc[2] + hb_s[n0]) * vs_s[n0]
                                   + fast_tanh(cc[3] + hb_s[n0 + 1]) * vs_s[n0 + 1];
                }
            }
        }
    }

    // ---- score reduce: t lanes (width 4), then 4 nw-warps via smem ----
#pragma unroll
    for (int i = 0; i < 4; ++i) {
        float v = s[i];
        v += __shfl_xor_sync(0xffffffffu, v, 1, 4);
        v += __shfl_xor_sync(0xffffffffu, v, 2, 4);
        if (t == 0) {
            int mt = i >> 1, half = i & 1;
            int row = mbase + mt * 16 + half * 8 + g;
            red[nw * 64 + row] = v;
        }
    }
    __syncthreads();

    // ---- publish this u-half's row-score partials ----
    const size_t pbase = ((size_t)(b * TCH + tc)) * 2 * TROWS;
    if (tid < TROWS) {
        float sum = red[tid] + red[64 + tid] + red[128 + tid] + red[192 + tid];
        g_spart[pbase + (size_t)uh * TROWS + tid] = sum;
    }
    __threadfence();
    __syncthreads();
    if (tid == 0) {
        isLast = atomicAdd(&g_flag[b * TCH + tc], 1);
    }
    __syncthreads();

    if (isLast == 1) {
        __threadfence();
        float* ws = hb_s;          // reuse
        if (tid < TROWS) {
            float sc = g_spart[pbase + tid] + g_spart[pbase + TROWS + tid];
            ws[tid] = expf(sc);    // bV cancels in softmax
        }
        __syncthreads();

        if (tid == 0) {
            float z = 0.f;
#pragma unroll
            for (int i = 0; i < TROWS; ++i) z += ws[i];
            g_zpart[b * TCH + tc] = z;
        }

        float2 cacc = make_float2(0.f, 0.f);
#pragma unroll 8
        for (int r = 0; r < TROWS; ++r) {
            __half2 a = *(const __half2*)(sA + r * PADA + 2 * tid);
            float2 f = __half22float2(a);
            float w = ws[r];
            cacc.x += w * f.x;
            cacc.y += w * f.y;
        }
        ((float2*)(g_part + ((size_t)(b * TCH + tc)) * DD))[tid] = cacc;
    }
}

// ---------------------------------------------------------------------------
// Kernel C: combine partials + Z, divide.  grid (4, BB) x 128 thr.
// ---------------------------------------------------------------------------
__global__ void k_combine(float* __restrict__ out) {
    int b = blockIdx.y;
    int d = blockIdx.x * 128 + threadIdx.x;
    __shared__ float zs;
    if (threadIdx.x == 0) {
        float z = 0.f;
#pragma unroll
        for (int tc = 0; tc < TCH; ++tc) z += g_zpart[b * TCH + tc];
        zs = z;
    }
    __syncthreads();
    float a0 = 0.f, a1 = 0.f;
#pragma unroll
    for (int tc = 0; tc < TCH; tc += 2) {
        a0 += g_part[((size_t)(b * TCH + tc)) * DD + d];
        a1 += g_part[((size_t)(b * TCH + tc + 1)) * DD + d];
    }
    out[b * DD + d] = (a0 + a1) / zs;
}

// ---------------------------------------------------------------------------
extern "C" void kernel_launch(void* const* d_in, const int* in_sizes, int n_in,
                              void* d_out, int out_size) {
    const float* full = (const float*)d_in[0];
    const float* last = (const float*)d_in[1];
    const float* W1   = (const float*)d_in[2];
    const float* b1   = (const float*)d_in[3];
    const float* W2   = (const float*)d_in[4];
    const float* b2   = (const float*)d_in[5];
    const float* V    = (const float*)d_in[6];
    float* out = (float*)d_out;

    cudaFuncSetAttribute(k_score, cudaFuncAttributeMaxDynamicSharedMemorySize,
                         SMEM_TOTAL);

    k_pre<<<257, 512>>>(W1, last, W2, b1, b2);

    dim3 gScore(TCH, BB, 2);
    k_score<<<gScore, 256, SMEM_TOTAL>>>(full, V);

    dim3 gComb(4, BB);
    k_combine<<<gComb, 128>>>(out);
}

// round 14
// speedup vs baseline: 1.8262x; 1.1178x over previous
#include <cuda_runtime.h>
#include <cuda_fp16.h>
#include <cstdint>
#include <math.h>

#define BB 32
#define TT 2048
#define DD 512
#define UU 512

#define TROWS 64
#define TCH (TT / TROWS)       // 32 chunks per batch

// ---- scratch ----
__device__ float g_hpart[BB * 8 * UU];   // split-k h2 partials (+b1+b2 in ks=0)
__device__ float g_zpart[BB * TCH];
__device__ float g_part[BB * TCH * DD];
__device__ int   g_bflag[BB];
__device__ __half g_w16[DD * UU];        // W1 fp16, native [d][u] layout

// ---------------- helpers ----------------
static __device__ __forceinline__ unsigned pack2h(__half a, __half b) {
    return (unsigned)__half_as_ushort(a) |
           ((unsigned)__half_as_ushort(b) << 16);
}
static __device__ __forceinline__ float fast_tanh(float x) {
    float e = __expf(2.f * x);
    return 1.f - __fdividef(2.f, e + 1.f);
}
static __device__ __forceinline__ void mma16816(float* c, const unsigned* a, const unsigned* b) {
    asm volatile(
        "mma.sync.aligned.m16n8k16.row.col.f32.f16.f16.f32 "
        "{%0,%1,%2,%3}, {%4,%5,%6,%7}, {%8,%9}, {%0,%1,%2,%3};"
        : "+f"(c[0]), "+f"(c[1]), "+f"(c[2]), "+f"(c[3])
        : "r"(a[0]), "r"(a[1]), "r"(a[2]), "r"(a[3]), "r"(b[0]), "r"(b[1]));
}
static __device__ __forceinline__ void ldm4(unsigned* r, const void* p) {
    unsigned addr = (unsigned)__cvta_generic_to_shared(p);
    asm volatile(
        "ldmatrix.sync.aligned.m8n8.x4.shared.b16 {%0,%1,%2,%3}, [%4];"
        : "=r"(r[0]), "=r"(r[1]), "=r"(r[2]), "=r"(r[3])
        : "r"(addr));
}
static __device__ __forceinline__ void ldm4t(unsigned* r, const void* p) {
    unsigned addr = (unsigned)__cvta_generic_to_shared(p);
    asm volatile(
        "ldmatrix.sync.aligned.m8n8.x4.trans.shared.b16 {%0,%1,%2,%3}, [%4];"
        : "=r"(r[0]), "=r"(r[1]), "=r"(r[2]), "=r"(r[3])
        : "r"(addr));
}
static __device__ __forceinline__ void cp16(void* dst, const void* src) {
    unsigned d = (unsigned)__cvta_generic_to_shared(dst);
    asm volatile("cp.async.cg.shared.global [%0], [%1], 16;"
                 :: "r"(d), "l"(src) : "memory");
}
static __device__ __forceinline__ void cp_commit() {
    asm volatile("cp.async.commit_group;" ::: "memory");
}
static __device__ __forceinline__ void cp_wait2() {
    asm volatile("cp.async.wait_group 2;" ::: "memory");
}
static __device__ __forceinline__ void cp_wait1() {
    asm volatile("cp.async.wait_group 1;" ::: "memory");
}
static __device__ __forceinline__ void cp_wait0() {
    asm volatile("cp.async.wait_group 0;" ::: "memory");
}

// smem layout (halves unless noted)
#define PADA 520
#define PADB2 136                  // 272 B row stride, mod 128 = 16 -> conflict-free
#define NSTAGE 4
#define OFF_HB   0
#define OFF_VS   512
#define OFF_RED  1024              // 256 floats
#define OFF_B    2048
#define B_STAGE_H (32 * PADB2)                         // 4352 halves = 8704 B
#define OFF_A    (OFF_B + NSTAGE * B_STAGE_H * 2)      // 36864
#define SMEM_TOTAL (OFF_A + TROWS * PADA * 2)          // 103424 B

// ---------------------------------------------------------------------------
// Kernel A: W1 fp32->fp16 convert + h2 split-k(8) partials + batch-flag reset
// grid 385 x 512 thr
// ---------------------------------------------------------------------------
__global__ void k_pre(const float* __restrict__ W1,
                      const float* __restrict__ last,
                      const float* __restrict__ W2,
                      const float* __restrict__ b1,
                      const float* __restrict__ b2) {
    if (blockIdx.x < 128) {
        int gidx = blockIdx.x * 2048 + threadIdx.x * 4;
        float4 v = *(const float4*)(W1 + gidx);
        uint2 hv;
        hv.x = pack2h(__float2half_rn(v.x), __float2half_rn(v.y));
        hv.y = pack2h(__float2half_rn(v.z), __float2half_rn(v.w));
        *(uint2*)(g_w16 + gidx) = hv;
    } else if (blockIdx.x < 384) {
        int bid = blockIdx.x - 128;      // 0..255
        int b  = bid >> 3;
        int ks = bid & 7;                // 8-way split-k, 64 d each
        int u  = threadIdx.x;
        __shared__ float sl[64];
        if (u < 64) sl[u] = last[b * DD + ks * 64 + u];
        __syncthreads();
        const float* w2p = W2 + (size_t)(ks * 64) * UU + u;
        float a0 = 0.f, a1 = 0.f, a2 = 0.f, a3 = 0.f;
#pragma unroll 4
        for (int d = 0; d < 64; d += 4) {
            a0 += sl[d + 0] * w2p[(size_t)(d + 0) * UU];
            a1 += sl[d + 1] * w2p[(size_t)(d + 1) * UU];
            a2 += sl[d + 2] * w2p[(size_t)(d + 2) * UU];
            a3 += sl[d + 3] * w2p[(size_t)(d + 3) * UU];
        }
        float acc = (a0 + a1) + (a2 + a3);
        if (ks == 0) acc += b1[u] + b2[u];
        g_hpart[(b * 8 + ks) * UU + u] = acc;
    } else {
        if (threadIdx.x < BB) g_bflag[threadIdx.x] = 0;
    }
}

// ---------------------------------------------------------------------------
// Kernel B: scores + fused partial context + fused final combine.
// CTA = 64t x 512u x 512k (R11 tiling).  A fp16 resident; B streamed via
// 4-stage cp.async ring consumed with ldmatrix.trans, one barrier/chunk.
// Last-finishing CTA per batch combines 32 partials and writes out.
// ---------------------------------------------------------------------------
__global__ __launch_bounds__(256, 2) void k_score(
    const float* __restrict__ full, const float* __restrict__ V,
    float* __restrict__ out) {
    extern __shared__ __align__(16) char smem[];
    float* hb_s = (float*)(smem + OFF_HB);
    float* vs_s = (float*)(smem + OFF_VS);
    float* red  = (float*)(smem + OFF_RED);
    __half* sB  = (__half*)(smem + OFF_B);
    __half* sA  = (__half*)(smem + OFF_A);
    __shared__ int isLast;
    __shared__ float zs;

    const int tid = threadIdx.x;
    const int wid = tid >> 5;
    const int lane = tid & 31;
    const int g = lane >> 2;
    const int t = lane & 3;
    const int mw = wid >> 2;        // 0..1 -> 32-row half
    const int nw = wid & 3;         // 0..3 -> 32-col u-tile
    const int mbase = mw * 32;
    const int nbase = nw * 32;

    const int b  = blockIdx.y;
    const int tc = blockIdx.x;
    const int t0 = tc * TROWS;

    const int tile = lane >> 3;
    const int rr = lane & 7;
    const int a_lane_off = ((tile & 1) * 8 + rr) * PADA + ((tile >> 1) & 1) * 8;
    const int bt_lane_off = ((tile & 1) * 8 + rr) * PADB2 + ((tile >> 1) & 1) * 8;

    auto issueB = [&](int gc, int slot) {
        const int u0 = (gc >> 4) * 128;
        const int k0 = (gc & 15) * 32;
#pragma unroll
        for (int j = 0; j < 2; ++j) {
            int o   = tid + j * 256;        // 0..511
            int row = o >> 4;               // k row 0..31
            int q   = o & 15;               // 16B chunk within 256B row
            const __half* src = g_w16 + (size_t)(k0 + row) * UU + u0 + q * 8;
            __half* dst = sB + slot * B_STAGE_H + row * PADB2 + q * 8;
            cp16(dst, src);
        }
        cp_commit();
    };

    issueB(0, 0);
    issueB(1, 1);
    issueB(2, 2);

    {
        const float* Ab = full + ((size_t)(b * TT + t0)) * DD;
#pragma unroll
        for (int it = 0; it < 32; ++it) {
            int idx = tid + it * 256;      // 0..8191 float4s
            int r = idx >> 7;
            int q = idx & 127;
            float4 v4 = *(const float4*)(Ab + (size_t)r * DD + q * 4);
            uint2 hv;
            hv.x = pack2h(__float2half_rn(v4.x), __float2half_rn(v4.y));
            hv.y = pack2h(__float2half_rn(v4.z), __float2half_rn(v4.w));
            *(uint2*)(sA + r * PADA + q * 4) = hv;
        }
    }

    float s[4];
#pragma unroll
    for (int i = 0; i < 4; ++i) s[i] = 0.f;
    float acc[32];

    for (int gc = 0; gc < 64; ++gc) {
        const int slot = gc & 3;
        if (gc <= 61) cp_wait2();
        else if (gc == 62) cp_wait1();
        else cp_wait0();
        __syncthreads();

        if ((gc & 15) == 0) {
            int uc = gc >> 4;
            if (tid < 128) {
                int u = uc * 128 + tid;
                float h = 0.f;
#pragma unroll
                for (int ks = 0; ks < 8; ++ks)
                    h += g_hpart[(b * 8 + ks) * UU + u];
                hb_s[tid] = h;
                vs_s[tid] = V[u];
            }
#pragma unroll
            for (int i = 0; i < 32; ++i) acc[i] = 0.f;
        }
        if (gc + 3 < 64) issueB(gc + 3, (gc + 3) & 3);

        const __half* Bh = sB + slot * B_STAGE_H;
        const int k0 = (gc & 15) * 32;
#pragma unroll
        for (int kk = 0; kk < 32; kk += 16) {
            unsigned bh[8];
#pragma unroll
            for (int p = 0; p < 2; ++p)
                ldm4t(bh + 4 * p, Bh + kk * PADB2 + nbase + p * 16 + bt_lane_off);
#pragma unroll
            for (int mt = 0; mt < 2; ++mt) {
                unsigned ah[4];
                ldm4(ah, sA + (mbase + mt * 16) * PADA + k0 + kk + a_lane_off);
#pragma unroll
                for (int nt = 0; nt < 4; ++nt)
                    mma16816(acc + (mt * 4 + nt) * 4, ah, bh + 2 * nt);
            }
        }

        if ((gc & 15) == 15) {
#pragma unroll
            for (int mt = 0; mt < 2; ++mt) {
#pragma unroll
                for (int nt = 0; nt < 4; ++nt) {
                    const float* cc = acc + (mt * 4 + nt) * 4;
                    int n0 = nbase + nt * 8 + 2 * t;
                    s[mt * 2 + 0] += fast_tanh(cc[0] + hb_s[n0]) * vs_s[n0]
                                   + fast_tanh(cc[1] + hb_s[n0 + 1]) * vs_s[n0 + 1];
                    s[mt * 2 + 1] += fast_tanh(cc[2] + hb_s[n0]) * vs_s[n0]
                                   + fast_tanh(cc[3] + hb_s[n0 + 1]) * vs_s[n0 + 1];
                }
            }
        }
    }

    // ---- score reduce: t lanes (width 4), then 4 nw-warps via smem ----
#pragma unroll
    for (int i = 0; i < 4; ++i) {
        float v = s[i];
        v += __shfl_xor_sync(0xffffffffu, v, 1, 4);
        v += __shfl_xor_sync(0xffffffffu, v, 2, 4);
        if (t == 0) {
            int mt = i >> 1, half = i & 1;
            int row = mbase + mt * 16 + half * 8 + g;
            red[nw * 64 + row] = v;
        }
    }
    __syncthreads();

    // ---- exp(score) per row (bV cancels in softmax) ----
    float* ws = hb_s;              // reuse
    if (tid < TROWS) {
        float sum = red[tid] + red[64 + tid] + red[128 + tid] + red[192 + tid];
        ws[tid] = expf(sum);
    }
    __syncthreads();

    if (tid == 0) {
        float z = 0.f;
#pragma unroll
        for (int i = 0; i < TROWS; ++i) z += ws[i];
        g_zpart[b * TCH + tc] = z;
    }

    // ---- partial weighted context from smem A tile (fp16) ----
    {
        float2 cacc = make_float2(0.f, 0.f);
#pragma unroll 8
        for (int r = 0; r < TROWS; ++r) {
            __half2 a = *(const __half2*)(sA + r * PADA + 2 * tid);
            float2 f = __half22float2(a);
            float w = ws[r];
            cacc.x += w * f.x;
            cacc.y += w * f.y;
        }
        ((float2*)(g_part + ((size_t)(b * TCH + tc)) * DD))[tid] = cacc;
    }

    // ---- batch-level rendezvous: last CTA of batch combines ----
    __threadfence();
    __syncthreads();
    if (tid == 0) isLast = atomicAdd(&g_bflag[b], 1);
    __syncthreads();

    if (isLast == TCH - 1) {
        __threadfence();
        if (tid == 0) {
            float z = 0.f;
#pragma unroll
            for (int c = 0; c < TCH; ++c) z += g_zpart[b * TCH + c];
            zs = z;
        }
        __syncthreads();
        float2 cacc = make_float2(0.f, 0.f);
#pragma unroll
        for (int c = 0; c < TCH; ++c) {
            float2 p = ((const float2*)(g_part + ((size_t)(b * TCH + c)) * DD))[tid];
            cacc.x += p.x;
            cacc.y += p.y;
        }
        float inv = 1.f / zs;
        ((float2*)(out + (size_t)b * DD))[tid] =
            make_float2(cacc.x * inv, cacc.y * inv);
    }
}

// ---------------------------------------------------------------------------
extern "C" void kernel_launch(void* const* d_in, const int* in_sizes, int n_in,
                              void* d_out, int out_size) {
    const float* full = (const float*)d_in[0];
    const float* last = (const float*)d_in[1];
    const float* W1   = (const float*)d_in[2];
    const float* b1   = (const float*)d_in[3];
    const float* W2   = (const float*)d_in[4];
    const float* b2   = (const float*)d_in[5];
    const float* V    = (const float*)d_in[6];
    float* out = (float*)d_out;

    cudaFuncSetAttribute(k_score, cudaFuncAttributeMaxDynamicSharedMemorySize,
                         SMEM_TOTAL);

    k_pre<<<385, 512>>>(W1, last, W2, b1, b2);

    dim3 gScore(TCH, BB);
    k_score<<<gScore, 256, SMEM_TOTAL>>>(full, V, out);
}

// round 15
// speedup vs baseline: 1.9092x; 1.0454x over previous
#include <cuda_runtime.h>
#include <cuda_fp16.h>
#include <cstdint>
#include <math.h>

#define BB 32
#define TT 2048
#define DD 512
#define UU 512

#define TROWS 64
#define TCH (TT / TROWS)       // 32 chunks per batch

// ---- scratch ----
__device__ float g_hpart[BB * 8 * UU];   // split-k h2 partials (+b1+b2 in ks=0)
__device__ float g_zpart[BB * TCH];
__device__ float g_part[BB * TCH * DD];
__device__ int   g_bflag[BB];
__device__ __half g_w16[DD * UU];        // W1 fp16, native [d][u] layout

// ---------------- helpers ----------------
static __device__ __forceinline__ unsigned pack2h(__half a, __half b) {
    return (unsigned)__half_as_ushort(a) |
           ((unsigned)__half_as_ushort(b) << 16);
}
static __device__ __forceinline__ float fast_tanh(float x) {
    float e = __expf(2.f * x);
    return 1.f - __fdividef(2.f, e + 1.f);
}
static __device__ __forceinline__ void mma16816(float* c, const unsigned* a, const unsigned* b) {
    asm volatile(
        "mma.sync.aligned.m16n8k16.row.col.f32.f16.f16.f32 "
        "{%0,%1,%2,%3}, {%4,%5,%6,%7}, {%8,%9}, {%0,%1,%2,%3};"
        : "+f"(c[0]), "+f"(c[1]), "+f"(c[2]), "+f"(c[3])
        : "r"(a[0]), "r"(a[1]), "r"(a[2]), "r"(a[3]), "r"(b[0]), "r"(b[1]));
}
static __device__ __forceinline__ void ldm4(unsigned* r, const void* p) {
    unsigned addr = (unsigned)__cvta_generic_to_shared(p);
    asm volatile(
        "ldmatrix.sync.aligned.m8n8.x4.shared.b16 {%0,%1,%2,%3}, [%4];"
        : "=r"(r[0]), "=r"(r[1]), "=r"(r[2]), "=r"(r[3])
        : "r"(addr));
}
static __device__ __forceinline__ void ldm4t(unsigned* r, const void* p) {
    unsigned addr = (unsigned)__cvta_generic_to_shared(p);
    asm volatile(
        "ldmatrix.sync.aligned.m8n8.x4.trans.shared.b16 {%0,%1,%2,%3}, [%4];"
        : "=r"(r[0]), "=r"(r[1]), "=r"(r[2]), "=r"(r[3])
        : "r"(addr));
}
static __device__ __forceinline__ void cp16(void* dst, const void* src) {
    unsigned d = (unsigned)__cvta_generic_to_shared(dst);
    asm volatile("cp.async.cg.shared.global [%0], [%1], 16;"
                 :: "r"(d), "l"(src) : "memory");
}
static __device__ __forceinline__ void cp_commit() {
    asm volatile("cp.async.commit_group;" ::: "memory");
}
static __device__ __forceinline__ void cp_wait0() {
    asm volatile("cp.async.wait_group 0;" ::: "memory");
}

// smem layout (halves unless noted)
#define PADA 520
#define PADB2 136                  // 272 B row stride, mod 128 = 16 -> conflict-free
#define BKC 64                     // k per chunk (doubled)
#define NSTAGE 2
#define OFF_HB   0
#define OFF_VS   512
#define OFF_RED  1024              // 256 floats
#define OFF_B    2048
#define B_STAGE_B (BKC * PADB2 * 2)                    // 17408 B per stage
#define OFF_A    (OFF_B + NSTAGE * B_STAGE_B)          // 36864
#define SMEM_TOTAL (OFF_A + TROWS * PADA * 2)          // 103424 B

// ---------------------------------------------------------------------------
// Kernel A: W1 fp32->fp16 convert + h2 split-k(8) partials + batch-flag reset
// ---------------------------------------------------------------------------
__global__ void k_pre(const float* __restrict__ W1,
                      const float* __restrict__ last,
                      const float* __restrict__ W2,
                      const float* __restrict__ b1,
                      const float* __restrict__ b2) {
    if (blockIdx.x < 128) {
        int gidx = blockIdx.x * 2048 + threadIdx.x * 4;
        float4 v = *(const float4*)(W1 + gidx);
        uint2 hv;
        hv.x = pack2h(__float2half_rn(v.x), __float2half_rn(v.y));
        hv.y = pack2h(__float2half_rn(v.z), __float2half_rn(v.w));
        *(uint2*)(g_w16 + gidx) = hv;
    } else if (blockIdx.x < 384) {
        int bid = blockIdx.x - 128;      // 0..255
        int b  = bid >> 3;
        int ks = bid & 7;
        int u  = threadIdx.x;
        __shared__ float sl[64];
        if (u < 64) sl[u] = last[b * DD + ks * 64 + u];
        __syncthreads();
        const float* w2p = W2 + (size_t)(ks * 64) * UU + u;
        float a0 = 0.f, a1 = 0.f, a2 = 0.f, a3 = 0.f;
#pragma unroll 4
        for (int d = 0; d < 64; d += 4) {
            a0 += sl[d + 0] * w2p[(size_t)(d + 0) * UU];
            a1 += sl[d + 1] * w2p[(size_t)(d + 1) * UU];
            a2 += sl[d + 2] * w2p[(size_t)(d + 2) * UU];
            a3 += sl[d + 3] * w2p[(size_t)(d + 3) * UU];
        }
        float acc = (a0 + a1) + (a2 + a3);
        if (ks == 0) acc += b1[u] + b2[u];
        g_hpart[(b * 8 + ks) * UU + u] = acc;
    } else {
        if (threadIdx.x < BB) g_bflag[threadIdx.x] = 0;
    }
}

// ---------------------------------------------------------------------------
// Kernel B: scores + fused partial context + fused final combine.
// CTA = 64t x 512u x 512k.  A fp16 resident.  B: 2-stage x k=64 cp.async
// double buffer (32 barriers instead of 64, 32-MMA runs per barrier).
// ---------------------------------------------------------------------------
__global__ __launch_bounds__(256, 2) void k_score(
    const float* __restrict__ full, const float* __restrict__ V,
    float* __restrict__ out) {
    extern __shared__ __align__(16) char smem[];
    float* hb_s = (float*)(smem + OFF_HB);
    float* vs_s = (float*)(smem + OFF_VS);
    float* red  = (float*)(smem + OFF_RED);
    __half* sA  = (__half*)(smem + OFF_A);
    __shared__ int isLast;
    __shared__ float zs;

    const int tid = threadIdx.x;
    const int wid = tid >> 5;
    const int lane = tid & 31;
    const int g = lane >> 2;
    const int t = lane & 3;
    const int mw = wid >> 2;        // 0..1 -> 32-row half
    const int nw = wid & 3;         // 0..3 -> 32-col u-tile
    const int mbase = mw * 32;
    const int nbase = nw * 32;

    const int b  = blockIdx.y;
    const int tc = blockIdx.x;
    const int t0 = tc * TROWS;

    const int tile = lane >> 3;
    const int rr = lane & 7;
    const int a_lane_off = ((tile & 1) * 8 + rr) * PADA + ((tile >> 1) & 1) * 8;
    const int bt_lane_off = ((tile & 1) * 8 + rr) * PADB2 + ((tile >> 1) & 1) * 8;

    // B stage base pointers (halves), hoisted
    __half* sB0 = (__half*)(smem + OFF_B);
    __half* sB1 = (__half*)(smem + OFF_B + B_STAGE_B);

    // chunk gc: uc = gc>>3 (u-pass of 128), kc = gc&7 (64-k slab)
    auto issueB = [&](int gc, __half* dstStage) {
        const int u0 = (gc >> 3) * 128;
        const int k0 = (gc & 7) * BKC;
#pragma unroll
        for (int j = 0; j < 4; ++j) {
            int o   = tid + j * 256;        // 0..1023
            int row = o >> 4;               // k row 0..63
            int q   = o & 15;               // 16B chunk within 256B row
            const __half* src = g_w16 + (size_t)(k0 + row) * UU + u0 + q * 8;
            cp16(dstStage + row * PADB2 + q * 8, src);
        }
        cp_commit();
    };

    issueB(0, sB0);

    {
        const float* Ab = full + ((size_t)(b * TT + t0)) * DD;
#pragma unroll
        for (int it = 0; it < 32; ++it) {
            int idx = tid + it * 256;      // 0..8191 float4s
            int r = idx >> 7;
            int q = idx & 127;
            float4 v4 = *(const float4*)(Ab + (size_t)r * DD + q * 4);
            uint2 hv;
            hv.x = pack2h(__float2half_rn(v4.x), __float2half_rn(v4.y));
            hv.y = pack2h(__float2half_rn(v4.z), __float2half_rn(v4.w));
            *(uint2*)(sA + r * PADA + q * 4) = hv;
        }
    }

    float s[4];
#pragma unroll
    for (int i = 0; i < 4; ++i) s[i] = 0.f;
    float acc[32];

    for (int gc = 0; gc < 32; ++gc) {
        cp_wait0();                 // chunk gc's data landed
        __syncthreads();            // visible to all; slot (gc+1)&1 free

        if ((gc & 7) == 0) {
            int uc = gc >> 3;
            if (tid < 128) {
                int u = uc * 128 + tid;
                float h = 0.f;
#pragma unroll
                for (int ks = 0; ks < 8; ++ks)
                    h += g_hpart[(b * 8 + ks) * UU + u];
                hb_s[tid] = h;
                vs_s[tid] = V[u];
            }
#pragma unroll
            for (int i = 0; i < 32; ++i) acc[i] = 0.f;
        }
        if (gc + 1 < 32) issueB(gc + 1, ((gc + 1) & 1) ? sB1 : sB0);

        const __half* Bh = (gc & 1) ? sB1 : sB0;
        const int k0 = (gc & 7) * BKC;
#pragma unroll
        for (int kk = 0; kk < BKC; kk += 16) {
            unsigned bh[8];
#pragma unroll
            for (int p = 0; p < 2; ++p)
                ldm4t(bh + 4 * p, Bh + kk * PADB2 + nbase + p * 16 + bt_lane_off);
#pragma unroll
            for (int mt = 0; mt < 2; ++mt) {
                unsigned ah[4];
                ldm4(ah, sA + (mbase + mt * 16) * PADA + k0 + kk + a_lane_off);
#pragma unroll
                for (int nt = 0; nt < 4; ++nt)
                    mma16816(acc + (mt * 4 + nt) * 4, ah, bh + 2 * nt);
            }
        }

        if ((gc & 7) == 7) {
#pragma unroll
            for (int mt = 0; mt < 2; ++mt) {
#pragma unroll
                for (int nt = 0; nt < 4; ++nt) {
                    const float* cc = acc + (mt * 4 + nt) * 4;
                    int n0 = nbase + nt * 8 + 2 * t;
                    s[mt * 2 + 0] += fast_tanh(cc[0] + hb_s[n0]) * vs_s[n0]
                                   + fast_tanh(cc[1] + hb_s[n0 + 1]) * vs_s[n0 + 1];
                    s[mt * 2 + 1] += fast_tanh(cc[2] + hb_s[n0]) * vs_s[n0]
                                   + fast_tanh(cc[3] + hb_s[n0 + 1]) * vs_s[n0 + 1];
                }
            }
        }
    }

    // ---- score reduce: t lanes (width 4), then 4 nw-warps via smem ----
#pragma unroll
    for (int i = 0; i < 4; ++i) {
        float v = s[i];
        v += __shfl_xor_sync(0xffffffffu, v, 1, 4);
        v += __shfl_xor_sync(0xffffffffu, v, 2, 4);
        if (t == 0) {
            int mt = i >> 1, half = i & 1;
            int row = mbase + mt * 16 + half * 8 + g;
            red[nw * 64 + row] = v;
        }
    }
    __syncthreads();

    // ---- exp(score) per row (bV cancels in softmax) ----
    float* ws = hb_s;              // reuse
    if (tid < TROWS) {
        float sum = red[tid] + red[64 + tid] + red[128 + tid] + red[192 + tid];
        ws[tid] = expf(sum);
    }
    __syncthreads();

    if (tid == 0) {
        float z = 0.f;
#pragma unroll
        for (int i = 0; i < TROWS; ++i) z += ws[i];
        g_zpart[b * TCH + tc] = z;
    }

    // ---- partial weighted context from smem A tile (fp16) ----
    {
        float2 cacc = make_float2(0.f, 0.f);
#pragma unroll 8
        for (int r = 0; r < TROWS; ++r) {
            __half2 a = *(const __half2*)(sA + r * PADA + 2 * tid);
            float2 f = __half22float2(a);
            float w = ws[r];
            cacc.x += w * f.x;
            cacc.y += w * f.y;
        }
        ((float2*)(g_part + ((size_t)(b * TCH + tc)) * DD))[tid] = cacc;
    }

    // ---- batch-level rendezvous: last CTA of batch combines ----
    __threadfence();
    __syncthreads();
    if (tid == 0) isLast = atomicAdd(&g_bflag[b], 1);
    __syncthreads();

    if (isLast == TCH - 1) {
        __threadfence();
        if (tid == 0) {
            float z = 0.f;
#pragma unroll
            for (int c = 0; c < TCH; ++c) z += g_zpart[b * TCH + c];
            zs = z;
        }
        __syncthreads();
        float2 cacc = make_float2(0.f, 0.f);
#pragma unroll
        for (int c = 0; c < TCH; ++c) {
            float2 p = ((const float2*)(g_part + ((size_t)(b * TCH + c)) * DD))[tid];
            cacc.x += p.x;
            cacc.y += p.y;
        }
        float inv = 1.f / zs;
        ((float2*)(out + (size_t)b * DD))[tid] =
            make_float2(cacc.x * inv, cacc.y * inv);
    }
}

// ---------------------------------------------------------------------------
extern "C" void kernel_launch(void* const* d_in, const int* in_sizes, int n_in,
                              void* d_out, int out_size) {
    const float* full = (const float*)d_in[0];
    const float* last = (const float*)d_in[1];
    const float* W1   = (const float*)d_in[2];
    const float* b1   = (const float*)d_in[3];
    const float* W2   = (const float*)d_in[4];
    const float* b2   = (const float*)d_in[5];
    const float* V    = (const float*)d_in[6];
    float* out = (float*)d_out;

    cudaFuncSetAttribute(k_score, cudaFuncAttributeMaxDynamicSharedMemorySize,
                         SMEM_TOTAL);

    k_pre<<<385, 512>>>(W1, last, W2, b1, b2);

    dim3 gScore(TCH, BB);
    k_score<<<gScore, 256, SMEM_TOTAL>>>(full, V, out);
}

// round 16
// speedup vs baseline: 1.9527x; 1.0228x over previous
#include <cuda_runtime.h>
#include <cuda_fp16.h>
#include <cstdint>
#include <math.h>

#define BB 32
#define TT 2048
#define DD 512
#define UU 512

#define TROWS 64
#define TCH (TT / TROWS)       // 32 chunks per batch

// ---- scratch ----
__device__ float g_hpart[BB * 8 * UU];
__device__ float g_zpart[BB * TCH];
__device__ float g_part[BB * TCH * DD];
__device__ int   g_bflag[BB];
__device__ __half g_w16[DD * UU];        // W1 fp16, native [d][u] layout

// ---------------- helpers ----------------
static __device__ __forceinline__ unsigned pack2h(__half a, __half b) {
    return (unsigned)__half_as_ushort(a) |
           ((unsigned)__half_as_ushort(b) << 16);
}
static __device__ __forceinline__ float fast_tanh(float x) {
    float e = __expf(2.f * x);
    return 1.f - __fdividef(2.f, e + 1.f);
}
static __device__ __forceinline__ void mma16816(float* c, const unsigned* a, const unsigned* b) {
    asm volatile(
        "mma.sync.aligned.m16n8k16.row.col.f32.f16.f16.f32 "
        "{%0,%1,%2,%3}, {%4,%5,%6,%7}, {%8,%9}, {%0,%1,%2,%3};"
        : "+f"(c[0]), "+f"(c[1]), "+f"(c[2]), "+f"(c[3])
        : "r"(a[0]), "r"(a[1]), "r"(a[2]), "r"(a[3]), "r"(b[0]), "r"(b[1]));
}
static __device__ __forceinline__ void ldm4_u32(unsigned* r, unsigned addr) {
    asm volatile(
        "ldmatrix.sync.aligned.m8n8.x4.shared.b16 {%0,%1,%2,%3}, [%4];"
        : "=r"(r[0]), "=r"(r[1]), "=r"(r[2]), "=r"(r[3])
        : "r"(addr));
}
static __device__ __forceinline__ void ldm4t_u32(unsigned* r, unsigned addr) {
    asm volatile(
        "ldmatrix.sync.aligned.m8n8.x4.trans.shared.b16 {%0,%1,%2,%3}, [%4];"
        : "=r"(r[0]), "=r"(r[1]), "=r"(r[2]), "=r"(r[3])
        : "r"(addr));
}
static __device__ __forceinline__ void cp16(void* dst, const void* src) {
    unsigned d = (unsigned)__cvta_generic_to_shared(dst);
    asm volatile("cp.async.cg.shared.global [%0], [%1], 16;"
                 :: "r"(d), "l"(src) : "memory");
}
static __device__ __forceinline__ void cp_commit() {
    asm volatile("cp.async.commit_group;" ::: "memory");
}
static __device__ __forceinline__ void cp_wait0() {
    asm volatile("cp.async.wait_group 0;" ::: "memory");
}

// smem layout
#define PADA 520                   // A row stride (halves)
#define PADB2 264                  // B k-row stride (halves): 528 B, %128=16
#define UPASS 256                  // u per pass
#define KCH 32                     // k per chunk
#define OFF_HB   0                 // 256 floats
#define OFF_VS   1024              // 256 floats
#define OFF_RED  2048              // 256 floats
#define OFF_B    3072
#define B_STAGE_B (KCH * PADB2 * 2)                    // 16896 B
#define OFF_A    (OFF_B + 2 * B_STAGE_B)               // 36864
#define SMEM_TOTAL (OFF_A + TROWS * PADA * 2)          // 103424 B

// ---------------------------------------------------------------------------
// Kernel A: W1 fp32->fp16 convert + h2 split-k(8) partials + batch-flag reset
// ---------------------------------------------------------------------------
__global__ void k_pre(const float* __restrict__ W1,
                      const float* __restrict__ last,
                      const float* __restrict__ W2,
                      const float* __restrict__ b1,
                      const float* __restrict__ b2) {
    if (blockIdx.x < 128) {
        int gidx = blockIdx.x * 2048 + threadIdx.x * 4;
        float4 v = *(const float4*)(W1 + gidx);
        uint2 hv;
        hv.x = pack2h(__float2half_rn(v.x), __float2half_rn(v.y));
        hv.y = pack2h(__float2half_rn(v.z), __float2half_rn(v.w));
        *(uint2*)(g_w16 + gidx) = hv;
    } else if (blockIdx.x < 384) {
        int bid = blockIdx.x - 128;
        int b  = bid >> 3;
        int ks = bid & 7;
        int u  = threadIdx.x;
        __shared__ float sl[64];
        if (u < 64) sl[u] = last[b * DD + ks * 64 + u];
        __syncthreads();
        const float* w2p = W2 + (size_t)(ks * 64) * UU + u;
        float a0 = 0.f, a1 = 0.f, a2 = 0.f, a3 = 0.f;
#pragma unroll 4
        for (int d = 0; d < 64; d += 4) {
            a0 += sl[d + 0] * w2p[(size_t)(d + 0) * UU];
            a1 += sl[d + 1] * w2p[(size_t)(d + 1) * UU];
            a2 += sl[d + 2] * w2p[(size_t)(d + 2) * UU];
            a3 += sl[d + 3] * w2p[(size_t)(d + 3) * UU];
        }
        float acc = (a0 + a1) + (a2 + a3);
        if (ks == 0) acc += b1[u] + b2[u];
        g_hpart[(b * 8 + ks) * UU + u] = acc;
    } else {
        if (threadIdx.x < BB) g_bflag[threadIdx.x] = 0;
    }
}

// ---------------------------------------------------------------------------
// Kernel B: scores + fused partial context + fused final combine.
// CTA = 64t x 512u x 512k.  Warp tile 32m x 64u (16 MMA per 6 LDSM).
// 2 u-passes of 256; B streamed 2-stage cp.async (k=32 chunks).
// ---------------------------------------------------------------------------
__global__ __launch_bounds__(256, 2) void k_score(
    const float* __restrict__ full, const float* __restrict__ V,
    float* __restrict__ out) {
    extern __shared__ __align__(16) char smem[];
    float* hb_s = (float*)(smem + OFF_HB);
    float* vs_s = (float*)(smem + OFF_VS);
    float* red  = (float*)(smem + OFF_RED);
    __half* sA  = (__half*)(smem + OFF_A);
    __shared__ int isLast;
    __shared__ float zs;

    const int tid = threadIdx.x;
    const int wid = tid >> 5;
    const int lane = tid & 31;
    const int g = lane >> 2;
    const int t = lane & 3;
    const int mw = wid >> 2;        // 0..1 -> 32-row half
    const int nw = wid & 3;         // 0..3 -> 64-col u-tile within 256 pass
    const int mbase = mw * 32;
    const int nbase = nw * 64;

    const int b  = blockIdx.y;
    const int tc = blockIdx.x;
    const int t0 = tc * TROWS;

    const int tile = lane >> 3;
    const int rr = lane & 7;
    const int a_lane_off = ((tile & 1) * 8 + rr) * PADA + ((tile >> 1) & 1) * 8;
    const int bt_lane_off = ((tile & 1) * 8 + rr) * PADB2 + ((tile >> 1) & 1) * 8;

    __half* sB0 = (__half*)(smem + OFF_B);
    __half* sB1 = (__half*)(smem + OFF_B + B_STAGE_B);

    // hoisted u32 smem addresses for ldmatrix
    const unsigned aBase = (unsigned)__cvta_generic_to_shared(sA)
                         + (unsigned)((mbase * PADA + a_lane_off) * 2);
    const unsigned bBase0 = (unsigned)__cvta_generic_to_shared(sB0)
                          + (unsigned)((nbase + bt_lane_off) * 2);
    const unsigned bBase1 = (unsigned)__cvta_generic_to_shared(sB1)
                          + (unsigned)((nbase + bt_lane_off) * 2);

    // chunk gc: pass = gc>>4 (256 u), kc = gc&15 (32-k slab)
    auto issueB = [&](int gc, __half* dstStage) {
        const int u0 = (gc >> 4) * UPASS;
        const int k0 = (gc & 15) * KCH;
#pragma unroll
        for (int j = 0; j < 4; ++j) {
            int o   = tid + j * 256;        // 0..1023
            int row = o >> 5;               // k row 0..31
            int q   = o & 31;               // 16B chunk within 512B row
            const __half* src = g_w16 + (size_t)(k0 + row) * UU + u0 + q * 8;
            cp16(dstStage + row * PADB2 + q * 8, src);
        }
        cp_commit();
    };

    issueB(0, sB0);

    {
        const float* Ab = full + ((size_t)(b * TT + t0)) * DD;
#pragma unroll
        for (int it = 0; it < 32; ++it) {
            int idx = tid + it * 256;
            int r = idx >> 7;
            int q = idx & 127;
            float4 v4 = *(const float4*)(Ab + (size_t)r * DD + q * 4);
            uint2 hv;
            hv.x = pack2h(__float2half_rn(v4.x), __float2half_rn(v4.y));
            hv.y = pack2h(__float2half_rn(v4.z), __float2half_rn(v4.w));
            *(uint2*)(sA + r * PADA + q * 4) = hv;
        }
    }

    float s[4];
#pragma unroll
    for (int i = 0; i < 4; ++i) s[i] = 0.f;
    float acc[64];

    for (int gc = 0; gc < 32; ++gc) {
        cp_wait0();
        __syncthreads();

        if ((gc & 15) == 0) {
            int pass = gc >> 4;
            {
                int u = pass * UPASS + tid;
                float h = 0.f;
#pragma unroll
                for (int ks = 0; ks < 8; ++ks)
                    h += g_hpart[(b * 8 + ks) * UU + u];
                hb_s[tid] = h;
                vs_s[tid] = V[u];
            }
#pragma unroll
            for (int i = 0; i < 64; ++i) acc[i] = 0.f;
        }
        if (gc + 1 < 32) issueB(gc + 1, ((gc + 1) & 1) ? sB1 : sB0);

        const unsigned bStage = (gc & 1) ? bBase1 : bBase0;
        const int k0 = (gc & 15) * KCH;
#pragma unroll
        for (int kk = 0; kk < KCH; kk += 16) {
            unsigned bh[16];
#pragma unroll
            for (int p = 0; p < 4; ++p)
                ldm4t_u32(bh + 4 * p,
                          bStage + (unsigned)((kk * PADB2 + p * 16) * 2));
#pragma unroll
            for (int mt = 0; mt < 2; ++mt) {
                unsigned ah[4];
                ldm4_u32(ah, aBase + (unsigned)((mt * 16 * PADA + k0 + kk) * 2));
#pragma unroll
                for (int nt = 0; nt < 8; ++nt)
                    mma16816(acc + (mt * 8 + nt) * 4, ah, bh + 2 * nt);
            }
        }

        if ((gc & 15) == 15) {
#pragma unroll
            for (int mt = 0; mt < 2; ++mt) {
#pragma unroll
                for (int nt = 0; nt < 8; ++nt) {
                    const float* cc = acc + (mt * 8 + nt) * 4;
                    int n0 = nbase + nt * 8 + 2 * t;
                    s[mt * 2 + 0] += fast_tanh(cc[0] + hb_s[n0]) * vs_s[n0]
                                   + fast_tanh(cc[1] + hb_s[n0 + 1]) * vs_s[n0 + 1];
                    s[mt * 2 + 1] += fast_tanh(cc[2] + hb_s[n0]) * vs_s[n0]
                                   + fast_tanh(cc[3] + hb_s[n0 + 1]) * vs_s[n0 + 1];
                }
            }
        }
    }

    // ---- score reduce: t lanes (width 4), then 4 nw-warps via smem ----
#pragma unroll
    for (int i = 0; i < 4; ++i) {
        float v = s[i];
        v += __shfl_xor_sync(0xffffffffu, v, 1, 4);
        v += __shfl_xor_sync(0xffffffffu, v, 2, 4);
        if (t == 0) {
            int mt = i >> 1, half = i & 1;
            int row = mbase + mt * 16 + half * 8 + g;
            red[nw * 64 + row] = v;
        }
    }
    __syncthreads();

    // ---- exp(score) per row (bV cancels in softmax) ----
    float* ws = hb_s;
    if (tid < TROWS) {
        float sum = red[tid] + red[64 + tid] + red[128 + tid] + red[192 + tid];
        ws[tid] = expf(sum);
    }
    __syncthreads();

    if (tid == 0) {
        float z = 0.f;
#pragma unroll
        for (int i = 0; i < TROWS; ++i) z += ws[i];
        g_zpart[b * TCH + tc] = z;
    }

    // ---- partial weighted context from smem A tile (fp16) ----
    {
        float2 cacc = make_float2(0.f, 0.f);
#pragma unroll 8
        for (int r = 0; r < TROWS; ++r) {
            __half2 a = *(const __half2*)(sA + r * PADA + 2 * tid);
            float2 f = __half22float2(a);
            float w = ws[r];
            cacc.x += w * f.x;
            cacc.y += w * f.y;
        }
        ((float2*)(g_part + ((size_t)(b * TCH + tc)) * DD))[tid] = cacc;
    }

    // ---- batch-level rendezvous: last CTA of batch combines ----
    __threadfence();
    __syncthreads();
    if (tid == 0) isLast = atomicAdd(&g_bflag[b], 1);
    __syncthreads();

    if (isLast == TCH - 1) {
        __threadfence();
        if (tid == 0) {
            float z = 0.f;
#pragma unroll
            for (int c = 0; c < TCH; ++c) z += g_zpart[b * TCH + c];
            zs = z;
        }
        __syncthreads();
        float2 cacc = make_float2(0.f, 0.f);
#pragma unroll
        for (int c = 0; c < TCH; ++c) {
            float2 p = ((const float2*)(g_part + ((size_t)(b * TCH + c)) * DD))[tid];
            cacc.x += p.x;
            cacc.y += p.y;
        }
        float inv = 1.f / zs;
        ((float2*)(out + (size_t)b * DD))[tid] =
            make_float2(cacc.x * inv, cacc.y * inv);
    }
}

// ---------------------------------------------------------------------------
extern "C" void kernel_launch(void* const* d_in, const int* in_sizes, int n_in,
                              void* d_out, int out_size) {
    const float* full = (const float*)d_in[0];
    const float* last = (const float*)d_in[1];
    const float* W1   = (const float*)d_in[2];
    const float* b1   = (const float*)d_in[3];
    const float* W2   = (const float*)d_in[4];
    const float* b2   = (const float*)d_in[5];
    const float* V    = (const float*)d_in[6];
    float* out = (float*)d_out;

    cudaFuncSetAttribute(k_score, cudaFuncAttributeMaxDynamicSharedMemorySize,
                         SMEM_TOTAL);

    k_pre<<<385, 512>>>(W1, last, W2, b1, b2);

    dim3 gScore(TCH, BB);
    k_score<<<gScore, 256, SMEM_TOTAL>>>(full, V, out);
}

// round 17
// speedup vs baseline: 2.0370x; 1.0432x over previous
#include <cuda_runtime.h>
#include <cuda_fp16.h>
#include <cstdint>
#include <math.h>

#define BB 32
#define TT 2048
#define DD 512
#define UU 512

#define TROWS 64
#define TCH (TT / TROWS)       // 32 chunks per batch

// ---- scratch ----
__device__ float g_hpart[BB * 8 * UU];
__device__ float g_zpart[BB * TCH];
__device__ float g_part[BB * TCH * DD];
__device__ int   g_bflag[BB];
__device__ __half g_w16[DD * UU];        // W1 fp16, native [d][u] layout

// ---------------- helpers ----------------
static __device__ __forceinline__ unsigned pack2h(__half a, __half b) {
    return (unsigned)__half_as_ushort(a) |
           ((unsigned)__half_as_ushort(b) << 16);
}
static __device__ __forceinline__ float fast_tanh(float x) {
    float e = __expf(2.f * x);
    return 1.f - __fdividef(2.f, e + 1.f);
}
static __device__ __forceinline__ void mma16816(float* c, const unsigned* a, const unsigned* b) {
    asm volatile(
        "mma.sync.aligned.m16n8k16.row.col.f32.f16.f16.f32 "
        "{%0,%1,%2,%3}, {%4,%5,%6,%7}, {%8,%9}, {%0,%1,%2,%3};"
        : "+f"(c[0]), "+f"(c[1]), "+f"(c[2]), "+f"(c[3])
        : "r"(a[0]), "r"(a[1]), "r"(a[2]), "r"(a[3]), "r"(b[0]), "r"(b[1]));
}
static __device__ __forceinline__ void ldm4_u32(unsigned* r, unsigned addr) {
    asm volatile(
        "ldmatrix.sync.aligned.m8n8.x4.shared.b16 {%0,%1,%2,%3}, [%4];"
        : "=r"(r[0]), "=r"(r[1]), "=r"(r[2]), "=r"(r[3])
        : "r"(addr));
}
static __device__ __forceinline__ void ldm4t_u32(unsigned* r, unsigned addr) {
    asm volatile(
        "ldmatrix.sync.aligned.m8n8.x4.trans.shared.b16 {%0,%1,%2,%3}, [%4];"
        : "=r"(r[0]), "=r"(r[1]), "=r"(r[2]), "=r"(r[3])
        : "r"(addr));
}
static __device__ __forceinline__ void cp16(void* dst, const void* src) {
    unsigned d = (unsigned)__cvta_generic_to_shared(dst);
    asm volatile("cp.async.cg.shared.global [%0], [%1], 16;"
                 :: "r"(d), "l"(src) : "memory");
}
static __device__ __forceinline__ void cp_commit() {
    asm volatile("cp.async.commit_group;" ::: "memory");
}
static __device__ __forceinline__ void cp_wait0() {
    asm volatile("cp.async.wait_group 0;" ::: "memory");
}

// smem layout
#define PADA 520                   // A row stride (halves)
#define PADB2 264                  // B k-row stride (halves): 528 B, %128=16
#define UPASS 256                  // u per pass
#define KCH 32                     // k per chunk
#define OFF_HB   0                 // 256 floats
#define OFF_VS   1024              // 256 floats
#define OFF_RED  2048              // 256 floats
#define OFF_B    3072
#define B_STAGE_B (KCH * PADB2 * 2)                    // 16896 B
#define OFF_A    (OFF_B + 2 * B_STAGE_B)               // 36864
#define SMEM_TOTAL (OFF_A + TROWS * PADA * 2)          // 103424 B

// ---------------------------------------------------------------------------
// Kernel A: W1 fp32->fp16 convert + h2 split-k(8) partials + batch-flag reset
// ---------------------------------------------------------------------------
__global__ void k_pre(const float* __restrict__ W1,
                      const float* __restrict__ last,
                      const float* __restrict__ W2,
                      const float* __restrict__ b1,
                      const float* __restrict__ b2) {
    if (blockIdx.x < 128) {
        int gidx = blockIdx.x * 2048 + threadIdx.x * 4;
        float4 v = *(const float4*)(W1 + gidx);
        uint2 hv;
        hv.x = pack2h(__float2half_rn(v.x), __float2half_rn(v.y));
        hv.y = pack2h(__float2half_rn(v.z), __float2half_rn(v.w));
        *(uint2*)(g_w16 + gidx) = hv;
    } else if (blockIdx.x < 384) {
        int bid = blockIdx.x - 128;
        int b  = bid >> 3;
        int ks = bid & 7;
        int u  = threadIdx.x;
        __shared__ float sl[64];
        if (u < 64) sl[u] = last[b * DD + ks * 64 + u];
        __syncthreads();
        const float* w2p = W2 + (size_t)(ks * 64) * UU + u;
        float a0 = 0.f, a1 = 0.f, a2 = 0.f, a3 = 0.f;
#pragma unroll 4
        for (int d = 0; d < 64; d += 4) {
            a0 += sl[d + 0] * w2p[(size_t)(d + 0) * UU];
            a1 += sl[d + 1] * w2p[(size_t)(d + 1) * UU];
            a2 += sl[d + 2] * w2p[(size_t)(d + 2) * UU];
            a3 += sl[d + 3] * w2p[(size_t)(d + 3) * UU];
        }
        float acc = (a0 + a1) + (a2 + a3);
        if (ks == 0) acc += b1[u] + b2[u];
        g_hpart[(b * 8 + ks) * UU + u] = acc;
    } else {
        if (threadIdx.x < BB) g_bflag[threadIdx.x] = 0;
    }
}

// ---------------------------------------------------------------------------
// Kernel B: scores + fused partial context + fused final combine.
// CTA = 64t x 512u x 512k.  Warp tile 32m x 64u.
// Phase-staggered: odd warps traverse kk in reverse + A-first fragment order;
// next-chunk cp.async issued mid-chunk to overlap with MMA phase.
// ---------------------------------------------------------------------------
__global__ __launch_bounds__(256, 2) void k_score(
    const float* __restrict__ full, const float* __restrict__ V,
    float* __restrict__ out) {
    extern __shared__ __align__(16) char smem[];
    float* hb_s = (float*)(smem + OFF_HB);
    float* vs_s = (float*)(smem + OFF_VS);
    float* red  = (float*)(smem + OFF_RED);
    __half* sA  = (__half*)(smem + OFF_A);
    __shared__ int isLast;
    __shared__ float zs;

    const int tid = threadIdx.x;
    const int wid = tid >> 5;
    const int lane = tid & 31;
    const int g = lane >> 2;
    const int t = lane & 3;
    const int mw = wid >> 2;        // 0..1 -> 32-row half
    const int nw = wid & 3;         // 0..3 -> 64-col u-tile within 256 pass
    const int mbase = mw * 32;
    const int nbase = nw * 64;
    const int oddw = wid & 1;       // stagger group

    const int b  = blockIdx.y;
    const int tc = blockIdx.x;
    const int t0 = tc * TROWS;

    const int tile = lane >> 3;
    const int rr = lane & 7;
    const int a_lane_off = ((tile & 1) * 8 + rr) * PADA + ((tile >> 1) & 1) * 8;
    const int bt_lane_off = ((tile & 1) * 8 + rr) * PADB2 + ((tile >> 1) & 1) * 8;

    __half* sB0 = (__half*)(smem + OFF_B);
    __half* sB1 = (__half*)(smem + OFF_B + B_STAGE_B);

    const unsigned aBase = (unsigned)__cvta_generic_to_shared(sA)
                         + (unsigned)((mbase * PADA + a_lane_off) * 2);
    const unsigned bBase0 = (unsigned)__cvta_generic_to_shared(sB0)
                          + (unsigned)((nbase + bt_lane_off) * 2);
    const unsigned bBase1 = (unsigned)__cvta_generic_to_shared(sB1)
                          + (unsigned)((nbase + bt_lane_off) * 2);

    auto issueB = [&](int gc, __half* dstStage) {
        const int u0 = (gc >> 4) * UPASS;
        const int k0 = (gc & 15) * KCH;
#pragma unroll
        for (int j = 0; j < 4; ++j) {
            int o   = tid + j * 256;        // 0..1023
            int row = o >> 5;               // k row 0..31
            int q   = o & 31;               // 16B chunk within 512B row
            const __half* src = g_w16 + (size_t)(k0 + row) * UU + u0 + q * 8;
            cp16(dstStage + row * PADB2 + q * 8, src);
        }
        cp_commit();
    };

    issueB(0, sB0);

    {
        const float* Ab = full + ((size_t)(b * TT + t0)) * DD;
#pragma unroll
        for (int it = 0; it < 32; ++it) {
            int idx = tid + it * 256;
            int r = idx >> 7;
            int q = idx & 127;
            float4 v4 = *(const float4*)(Ab + (size_t)r * DD + q * 4);
            uint2 hv;
            hv.x = pack2h(__float2half_rn(v4.x), __float2half_rn(v4.y));
            hv.y = pack2h(__float2half_rn(v4.z), __float2half_rn(v4.w));
            *(uint2*)(sA + r * PADA + q * 4) = hv;
        }
    }

    float s[4];
#pragma unroll
    for (int i = 0; i < 4; ++i) s[i] = 0.f;
    float acc[64];

    // one kk-step: loads fragments (order staggered by warp parity) + 16 MMA x2
    auto do_kk = [&](unsigned bStage, int k0, int kk) {
        unsigned bh[16];
        unsigned ah0[4], ah1[4];
        if (oddw) {
            ldm4_u32(ah0, aBase + (unsigned)((k0 + kk) * 2));
            ldm4_u32(ah1, aBase + (unsigned)((16 * PADA + k0 + kk) * 2));
#pragma unroll
            for (int p = 0; p < 4; ++p)
                ldm4t_u32(bh + 4 * p,
                          bStage + (unsigned)((kk * PADB2 + p * 16) * 2));
        } else {
#pragma unroll
            for (int p = 0; p < 4; ++p)
                ldm4t_u32(bh + 4 * p,
                          bStage + (unsigned)((kk * PADB2 + p * 16) * 2));
            ldm4_u32(ah0, aBase + (unsigned)((k0 + kk) * 2));
            ldm4_u32(ah1, aBase + (unsigned)((16 * PADA + k0 + kk) * 2));
        }
#pragma unroll
        for (int nt = 0; nt < 8; ++nt)
            mma16816(acc + nt * 4, ah0, bh + 2 * nt);
#pragma unroll
        for (int nt = 0; nt < 8; ++nt)
            mma16816(acc + (8 + nt) * 4, ah1, bh + 2 * nt);
    };

    for (int gc = 0; gc < 32; ++gc) {
        cp_wait0();
        __syncthreads();

        if ((gc & 15) == 0) {
            int pass = gc >> 4;
            {
                int u = pass * UPASS + tid;
                float h = 0.f;
#pragma unroll
                for (int ks = 0; ks < 8; ++ks)
                    h += g_hpart[(b * 8 + ks) * UU + u];
                hb_s[tid] = h;
                vs_s[tid] = V[u];
            }
#pragma unroll
            for (int i = 0; i < 64; ++i) acc[i] = 0.f;
        }

        const unsigned bStage = (gc & 1) ? bBase1 : bBase0;
        const int k0 = (gc & 15) * KCH;
        const int kkA = oddw ? 16 : 0;     // staggered traversal
        const int kkB = kkA ^ 16;

        do_kk(bStage, k0, kkA);
        // mid-chunk prefetch: lands during the MMA phase, off the LDSM burst
        if (gc + 1 < 32) issueB(gc + 1, ((gc + 1) & 1) ? sB1 : sB0);
        do_kk(bStage, k0, kkB);

        if ((gc & 15) == 15) {
#pragma unroll
            for (int mt = 0; mt < 2; ++mt) {
#pragma unroll
                for (int nt = 0; nt < 8; ++nt) {
                    const float* cc = acc + (mt * 8 + nt) * 4;
                    int n0 = nbase + nt * 8 + 2 * t;
                    s[mt * 2 + 0] += fast_tanh(cc[0] + hb_s[n0]) * vs_s[n0]
                                   + fast_tanh(cc[1] + hb_s[n0 + 1]) * vs_s[n0 + 1];
                    s[mt * 2 + 1] += fast_tanh(cc[2] + hb_s[n0]) * vs_s[n0]
                                   + fast_tanh(cc[3] + hb_s[n0 + 1]) * vs_s[n0 + 1];
                }
            }
        }
    }

    // ---- score reduce: t lanes (width 4), then 4 nw-warps via smem ----
#pragma unroll
    for (int i = 0; i < 4; ++i) {
        float v = s[i];
        v += __shfl_xor_sync(0xffffffffu, v, 1, 4);
        v += __shfl_xor_sync(0xffffffffu, v, 2, 4);
        if (t == 0) {
            int mt = i >> 1, half = i & 1;
            int row = mbase + mt * 16 + half * 8 + g;
            red[nw * 64 + row] = v;
        }
    }
    __syncthreads();

    // ---- exp(score) per row (bV cancels in softmax) ----
    float* ws = hb_s;
    if (tid < TROWS) {
        float sum = red[tid] + red[64 + tid] + red[128 + tid] + red[192 + tid];
        ws[tid] = expf(sum);
    }
    __syncthreads();

    if (tid == 0) {
        float z = 0.f;
#pragma unroll
        for (int i = 0; i < TROWS; ++i) z += ws[i];
        g_zpart[b * TCH + tc] = z;
    }

    // ---- partial weighted context from smem A tile (fp16) ----
    {
        float2 cacc = make_float2(0.f, 0.f);
#pragma unroll 8
        for (int r = 0; r < TROWS; ++r) {
            __half2 a = *(const __half2*)(sA + r * PADA + 2 * tid);
            float2 f = __half22float2(a);
            float w = ws[r];
            cacc.x += w * f.x;
            cacc.y += w * f.y;
        }
        ((float2*)(g_part + ((size_t)(b * TCH + tc)) * DD))[tid] = cacc;
    }

    // ---- batch-level rendezvous: last CTA of batch combines ----
    __threadfence();
    __syncthreads();
    if (tid == 0) isLast = atomicAdd(&g_bflag[b], 1);
    __syncthreads();

    if (isLast == TCH - 1) {
        __threadfence();
        if (tid == 0) {
            float z = 0.f;
#pragma unroll
            for (int c = 0; c < TCH; ++c) z += g_zpart[b * TCH + c];
            zs = z;
        }
        __syncthreads();
        float2 cacc = make_float2(0.f, 0.f);
#pragma unroll
        for (int c = 0; c < TCH; ++c) {
            float2 p = ((const float2*)(g_part + ((size_t)(b * TCH + c)) * DD))[tid];
            cacc.x += p.x;
            cacc.y += p.y;
        }
        float inv = 1.f / zs;
        ((float2*)(out + (size_t)b * DD))[tid] =
            make_float2(cacc.x * inv, cacc.y * inv);
    }
}

// ---------------------------------------------------------------------------
extern "C" void kernel_launch(void* const* d_in, const int* in_sizes, int n_in,
                              void* d_out, int out_size) {
    const float* full = (const float*)d_in[0];
    const float* last = (const float*)d_in[1];
    const float* W1   = (const float*)d_in[2];
    const float* b1   = (const float*)d_in[3];
    const float* W2   = (const float*)d_in[4];
    const float* b2   = (const float*)d_in[5];
    const float* V    = (const float*)d_in[6];
    float* out = (float*)d_out;

    cudaFuncSetAttribute(k_score, cudaFuncAttributeMaxDynamicSharedMemorySize,
                         SMEM_TOTAL);

    k_pre<<<385, 512>>>(W1, last, W2, b1, b2);

    dim3 gScore(TCH, BB);
    k_score<<<gScore, 256, SMEM_TOTAL>>>(full, V, out);
}